// round 2
// baseline (speedup 1.0000x reference)
#include <cuda_runtime.h>

// Problem constants
#define BB 64
#define NN 512
#define DD 128       // input feature dim
#define MM 128       // projection dim
#define NEG_INF -1e9f

// Scratch (device globals; no allocation allowed)
__device__ float g_mk[BB * NN * MM];   // masked key projection, 16.8 MB
__device__ float g_dot[BB * NN];       // per-row mq . mk
__device__ float g_qsum[BB * MM];      // per-batch sum of mq

__global__ void zero_qsum_kernel() {
    int i = blockIdx.x * blockDim.x + threadIdx.x;
    if (i < BB * MM) g_qsum[i] = 0.0f;
}

__device__ __forceinline__ float warp_sum(float v) {
#pragma unroll
    for (int o = 16; o; o >>= 1) v += __shfl_xor_sync(0xffffffffu, v, o);
    return v;
}

__device__ __forceinline__ float warp_max(float v) {
#pragma unroll
    for (int o = 16; o; o >>= 1) v = fmaxf(v, __shfl_xor_sync(0xffffffffu, v, o));
    return v;
}

// ---------------------------------------------------------------------------
// Kernel A: fused Q/K projection GEMM + masked stats.
// Block = 256 threads (8 warps), each warp computes 4 rows of q and k (128
// cols each). A row values are held in registers and broadcast via SHFL.
// W is read via LDG (128 KB total; stays L1/L2 resident).
// Emits: g_mk (mask*k), g_dot (mq.mk per row), g_qsum (atomics, per batch).
// ---------------------------------------------------------------------------
__global__ __launch_bounds__(256) void qk_kernel(
    const float* __restrict__ A, const float* __restrict__ mask,
    const float* __restrict__ Wq, const float* __restrict__ bq,
    const float* __restrict__ Wk, const float* __restrict__ bk)
{
    const int warp = threadIdx.x >> 5;
    const int lane = threadIdx.x & 31;
    const int row0 = blockIdx.x * 32 + warp * 4;     // 32 rows per block
    const int b = (blockIdx.x * 32) / NN;            // 16 blocks per batch

    const float4* A4 = (const float4*)A;
    float4 a[4];
#pragma unroll
    for (int r = 0; r < 4; r++) a[r] = A4[(size_t)(row0 + r) * 32 + lane];

    float accq[4][4], acck[4][4];
#pragma unroll
    for (int r = 0; r < 4; r++)
#pragma unroll
        for (int e = 0; e < 4; e++) { accq[r][e] = 0.0f; acck[r][e] = 0.0f; }

    const float4* Wq4 = (const float4*)Wq;
    const float4* Wk4 = (const float4*)Wk;

    for (int kt = 0; kt < DD; kt += 4) {
        const int src = kt >> 2;
#pragma unroll
        for (int s = 0; s < 4; s++) {
            float4 wq = Wq4[(kt + s) * 32 + lane];
            float4 wk = Wk4[(kt + s) * 32 + lane];
#pragma unroll
            for (int r = 0; r < 4; r++) {
                float av;
                if      (s == 0) av = __shfl_sync(0xffffffffu, a[r].x, src);
                else if (s == 1) av = __shfl_sync(0xffffffffu, a[r].y, src);
                else if (s == 2) av = __shfl_sync(0xffffffffu, a[r].z, src);
                else             av = __shfl_sync(0xffffffffu, a[r].w, src);
                accq[r][0] = fmaf(av, wq.x, accq[r][0]);
                accq[r][1] = fmaf(av, wq.y, accq[r][1]);
                accq[r][2] = fmaf(av, wq.z, accq[r][2]);
                accq[r][3] = fmaf(av, wq.w, accq[r][3]);
                acck[r][0] = fmaf(av, wk.x, acck[r][0]);
                acck[r][1] = fmaf(av, wk.y, acck[r][1]);
                acck[r][2] = fmaf(av, wk.z, acck[r][2]);
                acck[r][3] = fmaf(av, wk.w, acck[r][3]);
            }
        }
    }

    // Epilogue: bias, mask, store mk, per-row dot, per-block q_sum partials.
    float4 bq4 = ((const float4*)bq)[lane];
    float4 bk4 = ((const float4*)bk)[lane];

    __shared__ float sQ[8][128];
    float qs0 = 0.f, qs1 = 0.f, qs2 = 0.f, qs3 = 0.f;

#pragma unroll
    for (int r = 0; r < 4; r++) {
        int row = row0 + r;
        float m = mask[row];
        float mq0 = m * (accq[r][0] + bq4.x);
        float mq1 = m * (accq[r][1] + bq4.y);
        float mq2 = m * (accq[r][2] + bq4.z);
        float mq3 = m * (accq[r][3] + bq4.w);
        float mk0 = m * (acck[r][0] + bk4.x);
        float mk1 = m * (acck[r][1] + bk4.y);
        float mk2 = m * (acck[r][2] + bk4.z);
        float mk3 = m * (acck[r][3] + bk4.w);

        ((float4*)g_mk)[(size_t)row * 32 + lane] = make_float4(mk0, mk1, mk2, mk3);

        float p = mq0 * mk0 + mq1 * mk1 + mq2 * mk2 + mq3 * mk3;
        p = warp_sum(p);
        if (lane == 0) g_dot[row] = p;

        qs0 += mq0; qs1 += mq1; qs2 += mq2; qs3 += mq3;
    }

    ((float4*)sQ[warp])[lane] = make_float4(qs0, qs1, qs2, qs3);
    __syncthreads();

    if (threadIdx.x < 128) {
        int c = threadIdx.x;
        float s = 0.f;
#pragma unroll
        for (int w = 0; w < 8; w++) s += sQ[w][c];
        atomicAdd(&g_qsum[b * MM + c], s);
    }
}

// ---------------------------------------------------------------------------
// Kernel B: one block per batch. agg -> euclidean normalize -> masked softmax
// -> attn out; then context = sum_i attn_i * mk_i.
// ---------------------------------------------------------------------------
__global__ __launch_bounds__(256) void attn_kernel(
    const float* __restrict__ mask, float* __restrict__ out)
{
    const int b = blockIdx.x;
    const int warp = threadIdx.x >> 5;
    const int lane = threadIdx.x & 31;
    const int tid = threadIdx.x;

    __shared__ float sAgg[NN];
    __shared__ float sRed[8];
    __shared__ float sCtx[8][128];

    float4 qs = ((const float4*)g_qsum)[b * 32 + lane];
    const float4* mk4 = (const float4*)g_mk;
    const size_t base = (size_t)b * NN;

    // agg_i = mask_i * (mk_i . q_sum - dot_i)
    for (int i = warp; i < NN; i += 8) {
        float4 mk = mk4[(base + i) * 32 + lane];
        float p = mk.x * qs.x + mk.y * qs.y + mk.z * qs.z + mk.w * qs.w;
        p = warp_sum(p);
        if (lane == 0) sAgg[i] = mask[base + i] * (p - g_dot[base + i]);
    }
    __syncthreads();

    // sum of squares -> norm
    float ss = 0.f;
    for (int i = tid; i < NN; i += 256) { float v = sAgg[i]; ss += v * v; }
    ss = warp_sum(ss);
    if (lane == 0) sRed[warp] = ss;
    __syncthreads();
    float tot = 0.f;
#pragma unroll
    for (int w = 0; w < 8; w++) tot += sRed[w];
    float inv = 1.0f / sqrtf(tot);

    // scores (+mask penalty), block max
    float mx = -INFINITY;
    for (int i = tid; i < NN; i += 256) {
        float sc = sAgg[i] * inv + (1.0f - mask[base + i]) * NEG_INF;
        sAgg[i] = sc;
        mx = fmaxf(mx, sc);
    }
    mx = warp_max(mx);
    __syncthreads();
    if (lane == 0) sRed[warp] = mx;
    __syncthreads();
    float M = -INFINITY;
#pragma unroll
    for (int w = 0; w < 8; w++) M = fmaxf(M, sRed[w]);

    // exp & sum
    float es = 0.f;
    for (int i = tid; i < NN; i += 256) {
        float e = expf(sAgg[i] - M);
        sAgg[i] = e;
        es += e;
    }
    es = warp_sum(es);
    __syncthreads();
    if (lane == 0) sRed[warp] = es;
    __syncthreads();
    float S = 0.f;
#pragma unroll
    for (int w = 0; w < 8; w++) S += sRed[w];

    // attn out
    for (int i = tid; i < NN; i += 256) {
        float at = sAgg[i] / S;
        sAgg[i] = at;
        out[base + i] = at;
    }
    __syncthreads();

    // context = sum_i attn_i * mk_i   (mk already includes mask)
    float cx = 0.f, cy = 0.f, cz = 0.f, cw = 0.f;
    for (int i = warp; i < NN; i += 8) {
        float at = sAgg[i];
        float4 mk = mk4[(base + i) * 32 + lane];
        cx = fmaf(at, mk.x, cx);
        cy = fmaf(at, mk.y, cy);
        cz = fmaf(at, mk.z, cz);
        cw = fmaf(at, mk.w, cw);
    }
    ((float4*)sCtx[warp])[lane] = make_float4(cx, cy, cz, cw);
    __syncthreads();
    if (tid < 128) {
        float s = 0.f;
#pragma unroll
        for (int w = 0; w < 8; w++) s += sCtx[w][tid];
        out[(size_t)BB * NN + (size_t)b * MM + tid] = s;
    }
}

extern "C" void kernel_launch(void* const* d_in, const int* in_sizes, int n_in,
                              void* d_out, int out_size)
{
    const float* A    = (const float*)d_in[0];  // atom_query [B,N,D]
    const float* mask = (const float*)d_in[1];  // [B,N,1]
    const float* Wq   = (const float*)d_in[2];  // [D,DIM]
    const float* bq   = (const float*)d_in[3];  // [DIM]
    const float* Wk   = (const float*)d_in[4];  // [D,DIM]
    const float* bk   = (const float*)d_in[5];  // [DIM]
    float* out = (float*)d_out;                 // attn [B*N] then context [B*DIM]

    zero_qsum_kernel<<<32, 256>>>();
    qk_kernel<<<(BB * NN) / 32, 256>>>(A, mask, Wq, bq, Wk, bk);
    attn_kernel<<<BB, 256>>>(mask, out);
}

// round 3
// speedup vs baseline: 1.2422x; 1.2422x over previous
#include <cuda_runtime.h>
#include <math.h>

#define BB 64
#define NN 512
#define DD 128
#define MM 128
#define NEG_INF -1e9f

// Scratch (device globals)
__device__ float g_M[DD * DD];     // Mcol[e][d] = sum_m Wk[e,m]*Wq[d,m]
__device__ float g_WqT[MM * DD];   // WqT[m][d]
__device__ float g_WkT[MM * DD];   // WkT[m][d]
__device__ float g_G[BB * DD];     // per-batch vector: Wk*qsum - Wq*bk - Wk*bq
__device__ float g_C[BB];          // per-batch scalar: bk.qsum - bq.bk
__device__ float g_agg[BB * NN];   // pre-normalize agg
__device__ int   g_act[BB * NN];   // active row indices per batch
__device__ int   g_cnt[BB];        // active counts

__device__ __forceinline__ float warp_sum(float v) {
#pragma unroll
    for (int o = 16; o; o >>= 1) v += __shfl_xor_sync(0xffffffffu, v, o);
    return v;
}
__device__ __forceinline__ float warp_max(float v) {
#pragma unroll
    for (int o = 16; o; o >>= 1) v = fmaxf(v, __shfl_xor_sync(0xffffffffu, v, o));
    return v;
}

// ---------------------------------------------------------------------------
// K0a: transpose Wq, Wk (tiny)
// ---------------------------------------------------------------------------
__global__ void transpose_kernel(const float* __restrict__ Wq,
                                 const float* __restrict__ Wk) {
    int i = blockIdx.x * blockDim.x + threadIdx.x;   // 0 .. 2*16384
    int w = i >> 14;
    int r = (i >> 7) & 127;
    int c = i & 127;
    if (w == 0) g_WqT[c * DD + r] = Wq[r * MM + c];
    else        g_WkT[c * DD + r] = Wk[r * MM + c];
}

// ---------------------------------------------------------------------------
// K0b: Mcol[e][d] = sum_m Wk[e,m] * Wq[d,m]   (block per e, thread per d)
// ---------------------------------------------------------------------------
__global__ __launch_bounds__(128) void mcol_kernel(const float* __restrict__ Wk) {
    __shared__ float wk[MM];
    int e = blockIdx.x, d = threadIdx.x;
    wk[d] = Wk[e * MM + d];
    __syncthreads();
    float acc = 0.f;
#pragma unroll 8
    for (int m = 0; m < MM; m++) acc = fmaf(g_WqT[m * DD + d], wk[m], acc);
    g_M[e * DD + d] = acc;
}

// ---------------------------------------------------------------------------
// K1: per-batch stats. Block per batch (256 thr):
//   asum = sum_{mask} A_i, cnt, active index list, zero agg for masked rows,
//   qs = asum@Wq + cnt*bq, then G[d], C.
// ---------------------------------------------------------------------------
__global__ __launch_bounds__(256) void stats_kernel(
    const float* __restrict__ A, const float* __restrict__ mask,
    const float* __restrict__ Wq, const float* __restrict__ bq,
    const float* __restrict__ bk)
{
    const int b = blockIdx.x;
    const int warp = threadIdx.x >> 5, lane = threadIdx.x & 31, tid = threadIdx.x;
    const size_t base = (size_t)b * NN;
    const float4* A4 = (const float4*)A;

    __shared__ float sW[8][128];
    __shared__ float asum[128];
    __shared__ float qs[128];
    __shared__ int sact[NN];
    __shared__ int scnt;
    if (tid == 0) scnt = 0;
    __syncthreads();

    float4 acc = make_float4(0.f, 0.f, 0.f, 0.f);
    for (int i = warp; i < NN; i += 8) {
        float m = mask[base + i];
        if (m > 0.f) {
            float4 a = A4[(base + i) * 32 + lane];
            acc.x += a.x; acc.y += a.y; acc.z += a.z; acc.w += a.w;
            if (lane == 0) { int p = atomicAdd(&scnt, 1); sact[p] = i; }
        } else if (lane == 0) {
            g_agg[base + i] = 0.f;
        }
    }
    ((float4*)sW[warp])[lane] = acc;
    __syncthreads();

    if (tid < 128) {
        float s = 0.f;
#pragma unroll
        for (int w = 0; w < 8; w++) s += sW[w][tid];
        asum[tid] = s;
    }
    __syncthreads();

    const int nact = scnt;
    const float cnt = (float)nact;

    // qs[m] = sum_d asum[d]*Wq[d,m] + cnt*bq[m]
    if (tid < 128) {
        float q = cnt * bq[tid];
#pragma unroll 8
        for (int d = 0; d < DD; d++) q = fmaf(asum[d], Wq[d * MM + tid], q);
        qs[tid] = q;
    }
    __syncthreads();

    // C = sum_m bk[m]*(qs[m]-bq[m])
    if (warp == 0) {
        float c = 0.f;
        for (int m = lane; m < MM; m += 32) c = fmaf(bk[m], qs[m] - bq[m], c);
        c = warp_sum(c);
        if (lane == 0) g_C[b] = c;
    }

    // G[d] = sum_m WkT[m][d]*qs[m] - WqT[m][d]*bk[m]
    if (tid < 128) {
        float g = 0.f;
#pragma unroll 4
        for (int m = 0; m < MM; m++) {
            g = fmaf(g_WkT[m * DD + tid], qs[m], g);
            g = fmaf(g_WqT[m * DD + tid], -bk[m], g);
        }
        g_G[b * DD + tid] = g;
    }

    // publish active list
    for (int p = tid; p < nact; p += 256) g_act[base + p] = sact[p];
    if (tid == 0) g_cnt[b] = nact;
}

// ---------------------------------------------------------------------------
// K3: quadratic form on active rows only.
//   agg_i = A_i.G - A_i M A_i^T + C    (mask=1 for these rows)
// Grid = BB*8 blocks, 8 warps/block, 8 rows/warp.
// ---------------------------------------------------------------------------
__global__ __launch_bounds__(256) void quad_kernel(const float* __restrict__ A)
{
    const int warp = threadIdx.x >> 5, lane = threadIdx.x & 31;
    const int b = blockIdx.x >> 3;
    const int wg = ((blockIdx.x & 7) << 3) + warp;   // 0..63
    const int nact = g_cnt[b];
    const int j0 = wg * 8;
    if (j0 >= nact) return;

    const size_t base = (size_t)b * NN;
    const float4* A4 = (const float4*)A;
    const float4* M4 = (const float4*)g_M;

    float4 G = ((const float4*)(g_G + b * DD))[lane];
    const float C = g_C[b];

    int myidx = -1;
    if (lane < 8 && j0 + lane < nact) myidx = g_act[base + j0 + lane];

    float4 a[8], y[8];
#pragma unroll
    for (int r = 0; r < 8; r++) {
        int row = __shfl_sync(0xffffffffu, myidx, r);
        a[r] = (row >= 0) ? A4[(base + row) * 32 + lane] : make_float4(0.f, 0.f, 0.f, 0.f);
        y[r] = make_float4(0.f, 0.f, 0.f, 0.f);
    }

    for (int et = 0; et < DD; et += 4) {
        const int src = et >> 2;
#pragma unroll
        for (int s = 0; s < 4; s++) {
            float4 mc = M4[(et + s) * 32 + lane];
#pragma unroll
            for (int r = 0; r < 8; r++) {
                float av;
                if      (s == 0) av = __shfl_sync(0xffffffffu, a[r].x, src);
                else if (s == 1) av = __shfl_sync(0xffffffffu, a[r].y, src);
                else if (s == 2) av = __shfl_sync(0xffffffffu, a[r].z, src);
                else             av = __shfl_sync(0xffffffffu, a[r].w, src);
                y[r].x = fmaf(av, mc.x, y[r].x);
                y[r].y = fmaf(av, mc.y, y[r].y);
                y[r].z = fmaf(av, mc.z, y[r].z);
                y[r].w = fmaf(av, mc.w, y[r].w);
            }
        }
    }

#pragma unroll
    for (int r = 0; r < 8; r++) {
        int row = __shfl_sync(0xffffffffu, myidx, r);
        float p = a[r].x * (G.x - y[r].x) + a[r].y * (G.y - y[r].y)
                + a[r].z * (G.z - y[r].z) + a[r].w * (G.w - y[r].w);
        p = warp_sum(p);
        if (lane == 0 && row >= 0) g_agg[base + row] = p + C;
    }
}

// ---------------------------------------------------------------------------
// K4: per batch: normalize -> masked softmax -> attn out;
//     context = (sum_i attn_i A_i) @ Wk + (sum attn)*bk
// ---------------------------------------------------------------------------
__global__ __launch_bounds__(256) void softmax_ctx_kernel(
    const float* __restrict__ A, const float* __restrict__ mask,
    const float* __restrict__ Wk, const float* __restrict__ bk,
    float* __restrict__ out)
{
    const int b = blockIdx.x;
    const int warp = threadIdx.x >> 5, lane = threadIdx.x & 31, tid = threadIdx.x;
    const size_t base = (size_t)b * NN;
    const float4* A4 = (const float4*)A;

    __shared__ float sc[NN];
    __shared__ float sRed[8];
    __shared__ float sW[8][128];
    __shared__ float wsum[128];

    // sum of squares
    float ss = 0.f;
    for (int i = tid; i < NN; i += 256) {
        float v = g_agg[base + i];
        sc[i] = v;
        ss = fmaf(v, v, ss);
    }
    ss = warp_sum(ss);
    if (lane == 0) sRed[warp] = ss;
    __syncthreads();
    float tot = 0.f;
#pragma unroll
    for (int w = 0; w < 8; w++) tot += sRed[w];
    float inv = 1.0f / sqrtf(tot);

    // scores + max
    float mx = -INFINITY;
    for (int i = tid; i < NN; i += 256) {
        float m = mask[base + i];
        float s = (m > 0.f) ? sc[i] * inv : NEG_INF;
        sc[i] = s;
        mx = fmaxf(mx, s);
    }
    mx = warp_max(mx);
    __syncthreads();
    if (lane == 0) sRed[warp] = mx;
    __syncthreads();
    float M = -INFINITY;
#pragma unroll
    for (int w = 0; w < 8; w++) M = fmaxf(M, sRed[w]);

    // exp & sum
    float es = 0.f;
    for (int i = tid; i < NN; i += 256) {
        float e = expf(sc[i] - M);
        sc[i] = e;
        es += e;
    }
    es = warp_sum(es);
    __syncthreads();
    if (lane == 0) sRed[warp] = es;
    __syncthreads();
    float S = 0.f;
#pragma unroll
    for (int w = 0; w < 8; w++) S += sRed[w];
    float invS = 1.0f / S;

    // attn out + weighted sum of A
    float4 wacc = make_float4(0.f, 0.f, 0.f, 0.f);
    float wS = 0.f;
    for (int i = warp; i < NN; i += 8) {
        float at = sc[i] * invS;
        if (lane == 0) out[base + i] = at;
        if (at > 0.f) {
            float4 a = A4[(base + i) * 32 + lane];
            wacc.x = fmaf(at, a.x, wacc.x);
            wacc.y = fmaf(at, a.y, wacc.y);
            wacc.z = fmaf(at, a.z, wacc.z);
            wacc.w = fmaf(at, a.w, wacc.w);
            wS += at;
        }
    }
    ((float4*)sW[warp])[lane] = wacc;
    // reduce wS across block: reuse sRed
    wS = warp_sum(wS / 32.f);   // each lane counted once per row? no: wS identical per lane
    __syncthreads();
    if (lane == 0) sRed[warp] = wS;   // wS already full (same value in all lanes / summed)
    __syncthreads();
    if (tid < 128) {
        float s = 0.f;
#pragma unroll
        for (int w = 0; w < 8; w++) s += sW[w][tid];
        wsum[tid] = s;
    }
    float sumw = 0.f;
#pragma unroll
    for (int w = 0; w < 8; w++) sumw += sRed[w];
    __syncthreads();

    // context[m] = sum_d wsum[d]*Wk[d,m] + sumw*bk[m]
    if (tid < 128) {
        float c = sumw * bk[tid];
#pragma unroll 8
        for (int d = 0; d < DD; d++) c = fmaf(wsum[d], Wk[d * MM + tid], c);
        out[(size_t)BB * NN + (size_t)b * MM + tid] = c;
    }
}

extern "C" void kernel_launch(void* const* d_in, const int* in_sizes, int n_in,
                              void* d_out, int out_size)
{
    const float* A    = (const float*)d_in[0];
    const float* mask = (const float*)d_in[1];
    const float* Wq   = (const float*)d_in[2];
    const float* bq   = (const float*)d_in[3];
    const float* Wk   = (const float*)d_in[4];
    const float* bk   = (const float*)d_in[5];
    float* out = (float*)d_out;

    transpose_kernel<<<128, 256>>>(Wq, Wk);
    mcol_kernel<<<128, 128>>>(Wk);
    stats_kernel<<<BB, 256>>>(A, mask, Wq, bq, bk);
    quad_kernel<<<BB * 8, 256>>>(A);
    softmax_ctx_kernel<<<BB, 256>>>(A, mask, Wk, bk, out);
}

// round 4
// speedup vs baseline: 1.3943x; 1.1224x over previous
#include <cuda_runtime.h>
#include <math.h>

#define BB 64
#define NN 512
#define DD 128
#define MM 128
#define NEG_INF -1e9f

// Scratch (device globals)
__device__ float g_M[DD * DD];     // M[e][d] = sum_m Wk[e,m]*Wq[d,m]
__device__ float g_G[BB * DD];     // per-batch: G[d] = sum_m Wk[d,m]qs[m] - Wq[d,m]bk[m]
__device__ float g_C[BB];          // per-batch: bk.(qs-bq)
__device__ float g_agg[BB * NN];   // pre-normalize agg
__device__ int   g_act[BB * NN];   // active row indices per batch
__device__ int   g_cnt[BB];        // active counts

__device__ __forceinline__ float warp_sum(float v) {
#pragma unroll
    for (int o = 16; o; o >>= 1) v += __shfl_xor_sync(0xffffffffu, v, o);
    return v;
}
__device__ __forceinline__ float warp_max(float v) {
#pragma unroll
    for (int o = 16; o; o >>= 1) v = fmaxf(v, __shfl_xor_sync(0xffffffffu, v, o));
    return v;
}
__device__ __forceinline__ float dot4(float4 a, float4 b) {
    return a.x * b.x + a.y * b.y + a.z * b.z + a.w * b.w;
}

// ---------------------------------------------------------------------------
// K1: M[e][d] = Wk row e . Wq row d  (warp per e, coalesced float4 row loads)
// ---------------------------------------------------------------------------
__global__ __launch_bounds__(256) void mcol_kernel(
    const float* __restrict__ Wq, const float* __restrict__ Wk)
{
    const int warp = threadIdx.x >> 5, lane = threadIdx.x & 31;
    const int e = blockIdx.x * 8 + warp;           // grid 16 -> e in [0,128)
    const float4* Wq4 = (const float4*)Wq;
    const float4* Wk4 = (const float4*)Wk;

    float4 wk = Wk4[e * 32 + lane];
    for (int d = 0; d < DD; d += 2) {
        float p0 = dot4(wk, Wq4[d * 32 + lane]);
        float p1 = dot4(wk, Wq4[(d + 1) * 32 + lane]);
        p0 = warp_sum(p0);
        p1 = warp_sum(p1);
        if (lane == 0) { g_M[e * DD + d] = p0; g_M[e * DD + d + 1] = p1; }
    }
}

// ---------------------------------------------------------------------------
// K2: per-batch stats. Block per batch (256 thr):
//   asum, cnt, active list, zero agg for masked rows, qs, C, G.
// ---------------------------------------------------------------------------
__global__ __launch_bounds__(256) void stats_kernel(
    const float* __restrict__ A, const float* __restrict__ mask,
    const float* __restrict__ Wq, const float* __restrict__ Wk,
    const float* __restrict__ bq, const float* __restrict__ bk)
{
    const int b = blockIdx.x;
    const int warp = threadIdx.x >> 5, lane = threadIdx.x & 31, tid = threadIdx.x;
    const size_t base = (size_t)b * NN;
    const float4* A4 = (const float4*)A;
    const float4* Wq4 = (const float4*)Wq;
    const float4* Wk4 = (const float4*)Wk;

    __shared__ float sW[8][128];
    __shared__ float asum[128];
    __shared__ float qs[128];
    __shared__ int sact[NN];
    __shared__ int scnt;
    if (tid == 0) scnt = 0;
    __syncthreads();

    float4 acc = make_float4(0.f, 0.f, 0.f, 0.f);
    for (int i = warp; i < NN; i += 8) {
        float m = mask[base + i];
        if (m > 0.f) {
            float4 a = A4[(base + i) * 32 + lane];
            acc.x += a.x; acc.y += a.y; acc.z += a.z; acc.w += a.w;
            if (lane == 0) { int p = atomicAdd(&scnt, 1); sact[p] = i; }
        } else if (lane == 0) {
            g_agg[base + i] = 0.f;
        }
    }
    ((float4*)sW[warp])[lane] = acc;
    __syncthreads();

    if (tid < 128) {
        float s = 0.f;
#pragma unroll
        for (int w = 0; w < 8; w++) s += sW[w][tid];
        asum[tid] = s;
    }
    __syncthreads();

    const int nact = scnt;
    const float cnt = (float)nact;

    // qs[m] = sum_d asum[d]*Wq[d,m] + cnt*bq[m]   (coalesced column loads)
    if (tid < 128) {
        float q = cnt * bq[tid];
#pragma unroll 8
        for (int d = 0; d < DD; d++) q = fmaf(asum[d], Wq[d * MM + tid], q);
        qs[tid] = q;
    }
    __syncthreads();

    // C = sum_m bk[m]*(qs[m]-bq[m])
    if (warp == 0) {
        float c = 0.f;
        for (int m = lane; m < MM; m += 32) c = fmaf(bk[m], qs[m] - bq[m], c);
        c = warp_sum(c);
        if (lane == 0) g_C[b] = c;
    }

    // G[d] = Wk row d . qs  -  Wq row d . bk   (warp dot, coalesced rows)
    {
        float4 qs4 = ((const float4*)qs)[lane];
        float4 bk4 = ((const float4*)bk)[lane];
        for (int d = warp; d < DD; d += 8) {
            float p = dot4(Wk4[d * 32 + lane], qs4) - dot4(Wq4[d * 32 + lane], bk4);
            p = warp_sum(p);
            if (lane == 0) g_G[b * DD + d] = p;
        }
    }

    for (int p = tid; p < nact; p += 256) g_act[base + p] = sact[p];
    if (tid == 0) g_cnt[b] = nact;
}

// ---------------------------------------------------------------------------
// K3: quadratic form, smem-staged. agg_i = A_i.G - A_i M A_i^T + C
// Grid = BB*8, block 256 (8 warps * 8 rows = 64 rows/block).
// Dynamic smem: M 64KB | A rows 32KB | act 256B.
// ---------------------------------------------------------------------------
__global__ __launch_bounds__(256) void quad_kernel(const float* __restrict__ A)
{
    const int b = blockIdx.x >> 3;
    const int j0 = (blockIdx.x & 7) * 64;
    const int nact = g_cnt[b];
    if (j0 >= nact) return;

    extern __shared__ float4 smem4[];
    float4* sM4 = smem4;                 // [128][32] float4 = 64KB
    float4* sA4 = smem4 + 4096;          // [64][32] float4  = 32KB
    int* sAct = (int*)(smem4 + 4096 + 2048);

    const int warp = threadIdx.x >> 5, lane = threadIdx.x & 31, tid = threadIdx.x;
    const size_t base = (size_t)b * NN;
    const float4* A4 = (const float4*)A;
    const float4* gM4 = (const float4*)g_M;

    if (tid < 64) {
        int j = j0 + tid;
        sAct[tid] = (j < nact) ? g_act[base + j] : -1;
    }
#pragma unroll 4
    for (int idx = tid; idx < 4096; idx += 256) sM4[idx] = gM4[idx];
    __syncthreads();
#pragma unroll 2
    for (int idx = tid; idx < 2048; idx += 256) {
        int r = idx >> 5, c = idx & 31;
        int row = sAct[r];
        sA4[idx] = (row >= 0) ? A4[(base + row) * 32 + c]
                              : make_float4(0.f, 0.f, 0.f, 0.f);
    }
    __syncthreads();

    const int rbase = warp * 8;
    float4 y[8];
#pragma unroll
    for (int r = 0; r < 8; r++) y[r] = make_float4(0.f, 0.f, 0.f, 0.f);

    for (int e4 = 0; e4 < 32; e4++) {
        float4 av[8];
#pragma unroll
        for (int r = 0; r < 8; r++) av[r] = sA4[(rbase + r) * 32 + e4];  // LDS broadcast
#pragma unroll
        for (int s = 0; s < 4; s++) {
            float4 mc = sM4[(e4 * 4 + s) * 32 + lane];
#pragma unroll
            for (int r = 0; r < 8; r++) {
                float a = (s == 0) ? av[r].x : (s == 1) ? av[r].y
                        : (s == 2) ? av[r].z : av[r].w;
                y[r].x = fmaf(a, mc.x, y[r].x);
                y[r].y = fmaf(a, mc.y, y[r].y);
                y[r].z = fmaf(a, mc.z, y[r].z);
                y[r].w = fmaf(a, mc.w, y[r].w);
            }
        }
    }

    float4 G = ((const float4*)(g_G + b * DD))[lane];
    const float C = g_C[b];
#pragma unroll
    for (int r = 0; r < 8; r++) {
        int row = sAct[rbase + r];
        float4 a = sA4[(rbase + r) * 32 + lane];
        float p = a.x * (G.x - y[r].x) + a.y * (G.y - y[r].y)
                + a.z * (G.z - y[r].z) + a.w * (G.w - y[r].w);
        p = warp_sum(p);
        if (lane == 0 && row >= 0) g_agg[base + row] = p + C;
    }
}

// ---------------------------------------------------------------------------
// K4: normalize -> masked softmax -> attn out; context = wsum@Wk + bk
// (sum of attn is exactly 1, so the bias term is just bk)
// ---------------------------------------------------------------------------
__global__ __launch_bounds__(256) void softmax_ctx_kernel(
    const float* __restrict__ A, const float* __restrict__ mask,
    const float* __restrict__ Wk, const float* __restrict__ bk,
    float* __restrict__ out)
{
    const int b = blockIdx.x;
    const int warp = threadIdx.x >> 5, lane = threadIdx.x & 31, tid = threadIdx.x;
    const size_t base = (size_t)b * NN;
    const float4* A4 = (const float4*)A;

    __shared__ float sc[NN];
    __shared__ float sRed[8];
    __shared__ float sW[8][128];
    __shared__ float wsum[128];

    // sum of squares
    float ss = 0.f;
    for (int i = tid; i < NN; i += 256) {
        float v = g_agg[base + i];
        sc[i] = v;
        ss = fmaf(v, v, ss);
    }
    ss = warp_sum(ss);
    if (lane == 0) sRed[warp] = ss;
    __syncthreads();
    float tot = 0.f;
#pragma unroll
    for (int w = 0; w < 8; w++) tot += sRed[w];
    float inv = rsqrtf(tot);

    // scores + max
    float mx = -INFINITY;
    for (int i = tid; i < NN; i += 256) {
        float m = mask[base + i];
        float s = (m > 0.f) ? sc[i] * inv : NEG_INF;
        sc[i] = s;
        mx = fmaxf(mx, s);
    }
    mx = warp_max(mx);
    __syncthreads();
    if (lane == 0) sRed[warp] = mx;
    __syncthreads();
    float M = -INFINITY;
#pragma unroll
    for (int w = 0; w < 8; w++) M = fmaxf(M, sRed[w]);

    // exp & sum
    float es = 0.f;
    for (int i = tid; i < NN; i += 256) {
        float e = __expf(sc[i] - M);
        sc[i] = e;
        es += e;
    }
    es = warp_sum(es);
    __syncthreads();
    if (lane == 0) sRed[warp] = es;
    __syncthreads();
    float S = 0.f;
#pragma unroll
    for (int w = 0; w < 8; w++) S += sRed[w];
    float invS = 1.0f / S;

    // attn out (coalesced)
    for (int i = tid; i < NN; i += 256) {
        float at = sc[i] * invS;
        sc[i] = at;
        out[base + i] = at;
    }
    __syncthreads();

    // wsum[d] = sum_i attn_i * A_i[d]
    float4 wacc = make_float4(0.f, 0.f, 0.f, 0.f);
    for (int i = warp; i < NN; i += 8) {
        float at = sc[i];
        if (at > 0.f) {
            float4 a = A4[(base + i) * 32 + lane];
            wacc.x = fmaf(at, a.x, wacc.x);
            wacc.y = fmaf(at, a.y, wacc.y);
            wacc.z = fmaf(at, a.z, wacc.z);
            wacc.w = fmaf(at, a.w, wacc.w);
        }
    }
    ((float4*)sW[warp])[lane] = wacc;
    __syncthreads();
    if (tid < 128) {
        float s = 0.f;
#pragma unroll
        for (int w = 0; w < 8; w++) s += sW[w][tid];
        wsum[tid] = s;
    }
    __syncthreads();

    // context[m] = sum_d wsum[d]*Wk[d,m] + bk[m]
    if (tid < 128) {
        float c = bk[tid];
#pragma unroll 8
        for (int d = 0; d < DD; d++) c = fmaf(wsum[d], Wk[d * MM + tid], c);
        out[(size_t)BB * NN + (size_t)b * MM + tid] = c;
    }
}

extern "C" void kernel_launch(void* const* d_in, const int* in_sizes, int n_in,
                              void* d_out, int out_size)
{
    const float* A    = (const float*)d_in[0];
    const float* mask = (const float*)d_in[1];
    const float* Wq   = (const float*)d_in[2];
    const float* bq   = (const float*)d_in[3];
    const float* Wk   = (const float*)d_in[4];
    const float* bk   = (const float*)d_in[5];
    float* out = (float*)d_out;

    const int quad_smem = 4096 * 16 + 2048 * 16 + 256;   // 98560 B
    cudaFuncSetAttribute(quad_kernel,
                         cudaFuncAttributeMaxDynamicSharedMemorySize, quad_smem);

    mcol_kernel<<<16, 256>>>(Wq, Wk);
    stats_kernel<<<BB, 256>>>(A, mask, Wq, Wk, bq, bk);
    quad_kernel<<<BB * 8, 256, quad_smem>>>(A);
    softmax_ctx_kernel<<<BB, 256>>>(A, mask, Wk, bk, out);
}

// round 5
// speedup vs baseline: 1.6814x; 1.2060x over previous
#include <cuda_runtime.h>
#include <math.h>

#define BB 64
#define NN 512
#define DD 128
#define MM 128
#define NEG_INF -1e9f

// Scratch (device globals)
__device__ float g_M[DD * DD];     // M[e][d] = sum_m Wk[e,m]*Wq[d,m]
__device__ float g_G[BB * DD];     // per-batch: G[d] = Wk_row_d.qs - Wq_row_d.bk
__device__ float g_C[BB];          // per-batch: bk.(qs-bq)
__device__ float g_agg[BB * NN];   // pre-normalize agg
__device__ int   g_act[BB * NN];   // active row indices per batch
__device__ int   g_cnt[BB];        // active counts

__device__ __forceinline__ float warp_sum(float v) {
#pragma unroll
    for (int o = 16; o; o >>= 1) v += __shfl_xor_sync(0xffffffffu, v, o);
    return v;
}
__device__ __forceinline__ float warp_max(float v) {
#pragma unroll
    for (int o = 16; o; o >>= 1) v = fmaxf(v, __shfl_xor_sync(0xffffffffu, v, o));
    return v;
}
__device__ __forceinline__ float dot4(float4 a, float4 b) {
    return a.x * b.x + a.y * b.y + a.z * b.z + a.w * b.w;
}

// ---------------------------------------------------------------------------
// K1 (fused): blocks 0..63  -> per-batch stats (1024 threads, 32 warps)
//             blocks 64..67 -> M[e][d] = Wk row e . Wq row d (warp per e)
// ---------------------------------------------------------------------------
__global__ __launch_bounds__(1024) void prep_kernel(
    const float* __restrict__ A, const float* __restrict__ mask,
    const float* __restrict__ Wq, const float* __restrict__ Wk,
    const float* __restrict__ bq, const float* __restrict__ bk)
{
    const int warp = threadIdx.x >> 5, lane = threadIdx.x & 31, tid = threadIdx.x;
    const float4* Wq4 = (const float4*)Wq;
    const float4* Wk4 = (const float4*)Wk;

    if (blockIdx.x >= BB) {
        // ---- mcol part: 4 blocks * 32 warps = 128 e-rows ----
        const int e = (blockIdx.x - BB) * 32 + warp;
        float4 wk = Wk4[e * 32 + lane];
        for (int d = 0; d < DD; d += 2) {
            float p0 = dot4(wk, Wq4[d * 32 + lane]);
            float p1 = dot4(wk, Wq4[(d + 1) * 32 + lane]);
            p0 = warp_sum(p0);
            p1 = warp_sum(p1);
            if (lane == 0) { g_M[e * DD + d] = p0; g_M[e * DD + d + 1] = p1; }
        }
        return;
    }

    // ---- stats part ----
    const int b = blockIdx.x;
    const size_t base = (size_t)b * NN;
    const float4* A4 = (const float4*)A;

    __shared__ float sW[32][128];
    __shared__ float asum[128];
    __shared__ float qs[128];
    __shared__ int sact[NN];
    __shared__ int scnt;
    if (tid == 0) scnt = 0;
    __syncthreads();

    float4 acc = make_float4(0.f, 0.f, 0.f, 0.f);
#pragma unroll
    for (int i = warp; i < NN; i += 32) {
        float m = mask[base + i];
        if (m > 0.f) {
            float4 a = A4[(base + i) * 32 + lane];
            acc.x += a.x; acc.y += a.y; acc.z += a.z; acc.w += a.w;
            if (lane == 0) { int p = atomicAdd(&scnt, 1); sact[p] = i; }
        } else if (lane == 0) {
            g_agg[base + i] = 0.f;
        }
    }
    ((float4*)sW[warp])[lane] = acc;
    __syncthreads();

    if (tid < 128) {
        float s = 0.f;
#pragma unroll
        for (int w = 0; w < 32; w++) s += sW[w][tid];
        asum[tid] = s;
    }
    __syncthreads();

    const int nact = scnt;
    const float cnt = (float)nact;

    // qs[m] = sum_d asum[d]*Wq[d,m] + cnt*bq[m]
    if (tid < 128) {
        float q = cnt * bq[tid];
#pragma unroll 8
        for (int d = 0; d < DD; d++) q = fmaf(asum[d], Wq[d * MM + tid], q);
        qs[tid] = q;
    }
    __syncthreads();

    // C = sum_m bk[m]*(qs[m]-bq[m])
    if (warp == 0) {
        float c = 0.f;
        for (int m = lane; m < MM; m += 32) c = fmaf(bk[m], qs[m] - bq[m], c);
        c = warp_sum(c);
        if (lane == 0) g_C[b] = c;
    }

    // G[d] = Wk row d . qs - Wq row d . bk  (warp per d, 4 rows/warp)
    {
        float4 qs4 = ((const float4*)qs)[lane];
        float4 bk4 = ((const float4*)bk)[lane];
#pragma unroll
        for (int d = warp; d < DD; d += 32) {
            float p = dot4(Wk4[d * 32 + lane], qs4) - dot4(Wq4[d * 32 + lane], bk4);
            p = warp_sum(p);
            if (lane == 0) g_G[b * DD + d] = p;
        }
    }

    for (int p = tid; p < nact; p += 1024) g_act[base + p] = sact[p];
    if (tid == 0) g_cnt[b] = nact;
}

// ---------------------------------------------------------------------------
// K2: quadratic form, smem-staged. agg_i = A_i.G - A_i M A_i^T + C
// Grid = BB*8, block 256 (8 warps * 8 rows = 64 rows/block).
// ---------------------------------------------------------------------------
__global__ __launch_bounds__(256) void quad_kernel(const float* __restrict__ A)
{
    const int b = blockIdx.x >> 3;
    const int j0 = (blockIdx.x & 7) * 64;
    const int nact = g_cnt[b];
    if (j0 >= nact) return;

    extern __shared__ float4 smem4[];
    float4* sM4 = smem4;                 // [128][32] float4 = 64KB
    float4* sA4 = smem4 + 4096;          // [64][32] float4  = 32KB
    int* sAct = (int*)(smem4 + 4096 + 2048);

    const int warp = threadIdx.x >> 5, lane = threadIdx.x & 31, tid = threadIdx.x;
    const size_t base = (size_t)b * NN;
    const float4* A4 = (const float4*)A;
    const float4* gM4 = (const float4*)g_M;

    if (tid < 64) {
        int j = j0 + tid;
        sAct[tid] = (j < nact) ? g_act[base + j] : -1;
    }
#pragma unroll 4
    for (int idx = tid; idx < 4096; idx += 256) sM4[idx] = gM4[idx];
    __syncthreads();
#pragma unroll 2
    for (int idx = tid; idx < 2048; idx += 256) {
        int r = idx >> 5, c = idx & 31;
        int row = sAct[r];
        sA4[idx] = (row >= 0) ? A4[(base + row) * 32 + c]
                              : make_float4(0.f, 0.f, 0.f, 0.f);
    }
    __syncthreads();

    const int rbase = warp * 8;
    float4 y[8];
#pragma unroll
    for (int r = 0; r < 8; r++) y[r] = make_float4(0.f, 0.f, 0.f, 0.f);

    for (int e4 = 0; e4 < 32; e4++) {
        float4 av[8];
#pragma unroll
        for (int r = 0; r < 8; r++) av[r] = sA4[(rbase + r) * 32 + e4];
#pragma unroll
        for (int s = 0; s < 4; s++) {
            float4 mc = sM4[(e4 * 4 + s) * 32 + lane];
#pragma unroll
            for (int r = 0; r < 8; r++) {
                float a = (s == 0) ? av[r].x : (s == 1) ? av[r].y
                        : (s == 2) ? av[r].z : av[r].w;
                y[r].x = fmaf(a, mc.x, y[r].x);
                y[r].y = fmaf(a, mc.y, y[r].y);
                y[r].z = fmaf(a, mc.z, y[r].z);
                y[r].w = fmaf(a, mc.w, y[r].w);
            }
        }
    }

    float4 G = ((const float4*)(g_G + b * DD))[lane];
    const float C = g_C[b];
#pragma unroll
    for (int r = 0; r < 8; r++) {
        int row = sAct[rbase + r];
        float4 a = sA4[(rbase + r) * 32 + lane];
        float p = a.x * (G.x - y[r].x) + a.y * (G.y - y[r].y)
                + a.z * (G.z - y[r].z) + a.w * (G.w - y[r].w);
        p = warp_sum(p);
        if (lane == 0 && row >= 0) g_agg[base + row] = p + C;
    }
}

// ---------------------------------------------------------------------------
// K3: normalize -> masked softmax -> attn out; context = wsum@Wk + bk
// 1024 threads per block for memory-level parallelism.
// ---------------------------------------------------------------------------
__global__ __launch_bounds__(1024) void softmax_ctx_kernel(
    const float* __restrict__ A, const float* __restrict__ mask,
    const float* __restrict__ Wk, const float* __restrict__ bk,
    float* __restrict__ out)
{
    const int b = blockIdx.x;
    const int warp = threadIdx.x >> 5, lane = threadIdx.x & 31, tid = threadIdx.x;
    const size_t base = (size_t)b * NN;
    const float4* A4 = (const float4*)A;

    __shared__ float sc[NN];
    __shared__ float sRed[32];
    __shared__ float sW[32][128];
    __shared__ float wsum[128];

    // sum of squares
    float ss = 0.f;
    for (int i = tid; i < NN; i += 1024) {
        float v = g_agg[base + i];
        sc[i] = v;
        ss = fmaf(v, v, ss);
    }
    ss = warp_sum(ss);
    if (lane == 0) sRed[warp] = ss;
    __syncthreads();
    float tot = 0.f;
#pragma unroll
    for (int w = 0; w < 32; w++) tot += sRed[w];
    float inv = rsqrtf(tot);

    // scores + max
    float mx = -INFINITY;
    for (int i = tid; i < NN; i += 1024) {
        float m = mask[base + i];
        float s = (m > 0.f) ? sc[i] * inv : NEG_INF;
        sc[i] = s;
        mx = fmaxf(mx, s);
    }
    mx = warp_max(mx);
    __syncthreads();
    if (lane == 0) sRed[warp] = mx;
    __syncthreads();
    float M = -INFINITY;
#pragma unroll
    for (int w = 0; w < 32; w++) M = fmaxf(M, sRed[w]);

    // exp & sum
    float es = 0.f;
    for (int i = tid; i < NN; i += 1024) {
        float e = __expf(sc[i] - M);
        sc[i] = e;
        es += e;
    }
    es = warp_sum(es);
    __syncthreads();
    if (lane == 0) sRed[warp] = es;
    __syncthreads();
    float S = 0.f;
#pragma unroll
    for (int w = 0; w < 32; w++) S += sRed[w];
    float invS = 1.0f / S;

    // attn out (coalesced)
    for (int i = tid; i < NN; i += 1024) {
        float at = sc[i] * invS;
        sc[i] = at;
        out[base + i] = at;
    }
    __syncthreads();

    // wsum[d] = sum_i attn_i * A_i[d]   (32 warps, 16 rows each)
    float4 wacc = make_float4(0.f, 0.f, 0.f, 0.f);
#pragma unroll
    for (int i = warp; i < NN; i += 32) {
        float at = sc[i];
        if (at > 0.f) {
            float4 a = A4[(base + i) * 32 + lane];
            wacc.x = fmaf(at, a.x, wacc.x);
            wacc.y = fmaf(at, a.y, wacc.y);
            wacc.z = fmaf(at, a.z, wacc.z);
            wacc.w = fmaf(at, a.w, wacc.w);
        }
    }
    ((float4*)sW[warp])[lane] = wacc;
    __syncthreads();
    if (tid < 128) {
        float s = 0.f;
#pragma unroll
        for (int w = 0; w < 32; w++) s += sW[w][tid];
        wsum[tid] = s;
    }
    __syncthreads();

    // context[m] = sum_d wsum[d]*Wk[d,m] + bk[m]
    if (tid < 128) {
        float c = bk[tid];
#pragma unroll 8
        for (int d = 0; d < DD; d++) c = fmaf(wsum[d], Wk[d * MM + tid], c);
        out[(size_t)BB * NN + (size_t)b * MM + tid] = c;
    }
}

extern "C" void kernel_launch(void* const* d_in, const int* in_sizes, int n_in,
                              void* d_out, int out_size)
{
    const float* A    = (const float*)d_in[0];
    const float* mask = (const float*)d_in[1];
    const float* Wq   = (const float*)d_in[2];
    const float* bq   = (const float*)d_in[3];
    const float* Wk   = (const float*)d_in[4];
    const float* bk   = (const float*)d_in[5];
    float* out = (float*)d_out;

    const int quad_smem = 4096 * 16 + 2048 * 16 + 256;   // 98560 B
    cudaFuncSetAttribute(quad_kernel,
                         cudaFuncAttributeMaxDynamicSharedMemorySize, quad_smem);

    prep_kernel<<<BB + 4, 1024>>>(A, mask, Wq, Wk, bq, bk);
    quad_kernel<<<BB * 8, 256, quad_smem>>>(A);
    softmax_ctx_kernel<<<BB, 1024>>>(A, mask, Wk, bk, out);
}

// round 6
// speedup vs baseline: 1.7155x; 1.0202x over previous
#include <cuda_runtime.h>
#include <math.h>

#define BB 64
#define NN 512
#define DD 128
#define MM 128
#define NEG_INF -1e9f

// Scratch (device globals)
__device__ float g_M[DD * DD];     // M[e][d] = sum_m Wk[e,m]*Wq[d,m]
__device__ float g_G[BB * DD];     // per-batch: G[d] = Wk_row_d.qs - Wq_row_d.bk
__device__ float g_C[BB];          // per-batch: bk.(qs-bq)
__device__ float g_agg[BB * NN];   // pre-normalize agg
__device__ int   g_act[BB * NN];   // active row indices per batch
__device__ int   g_cnt[BB];        // active counts

__device__ __forceinline__ float warp_sum(float v) {
#pragma unroll
    for (int o = 16; o; o >>= 1) v += __shfl_xor_sync(0xffffffffu, v, o);
    return v;
}
__device__ __forceinline__ float warp_max(float v) {
#pragma unroll
    for (int o = 16; o; o >>= 1) v = fmaxf(v, __shfl_xor_sync(0xffffffffu, v, o));
    return v;
}
__device__ __forceinline__ float dot4(float4 a, float4 b) {
    return a.x * b.x + a.y * b.y + a.z * b.z + a.w * b.w;
}

// ---------------------------------------------------------------------------
// K1 (fused): blocks 0..63  -> per-batch stats (1024 threads, branchless)
//             blocks 64..67 -> M[e][d] = Wk row e . Wq row d (warp per e)
// ---------------------------------------------------------------------------
__global__ __launch_bounds__(1024) void prep_kernel(
    const float* __restrict__ A, const float* __restrict__ mask,
    const float* __restrict__ Wq, const float* __restrict__ Wk,
    const float* __restrict__ bq, const float* __restrict__ bk)
{
    const int warp = threadIdx.x >> 5, lane = threadIdx.x & 31, tid = threadIdx.x;
    const float4* Wq4 = (const float4*)Wq;
    const float4* Wk4 = (const float4*)Wk;

    if (blockIdx.x >= BB) {
        // ---- mcol part: 4 blocks * 32 warps = 128 e-rows ----
        const int e = (blockIdx.x - BB) * 32 + warp;
        float4 wk = Wk4[e * 32 + lane];
        for (int d = 0; d < DD; d += 2) {
            float p0 = dot4(wk, Wq4[d * 32 + lane]);
            float p1 = dot4(wk, Wq4[(d + 1) * 32 + lane]);
            p0 = warp_sum(p0);
            p1 = warp_sum(p1);
            if (lane == 0) { g_M[e * DD + d] = p0; g_M[e * DD + d + 1] = p1; }
        }
        return;
    }

    // ---- stats part ----
    const int b = blockIdx.x;
    const size_t base = (size_t)b * NN;
    const float4* A4 = (const float4*)A;

    __shared__ float sW[32][128];
    __shared__ float asum[128];
    __shared__ float qs[128];

    // Branchless masked sum: all loads independent -> high MLP.
    float4 acc = make_float4(0.f, 0.f, 0.f, 0.f);
#pragma unroll
    for (int i = warp; i < NN; i += 32) {
        float m = mask[base + i];
        float4 a = A4[(base + i) * 32 + lane];
        acc.x = fmaf(m, a.x, acc.x);
        acc.y = fmaf(m, a.y, acc.y);
        acc.z = fmaf(m, a.z, acc.z);
        acc.w = fmaf(m, a.w, acc.w);
    }
    ((float4*)sW[warp])[lane] = acc;

    // Zero agg for all rows (quad overwrites active ones).
    for (int i = tid; i < NN; i += 1024) g_agg[base + i] = 0.f;

    // Warp 0: ballot-based active-list compaction, no atomics.
    if (warp == 0) {
        int cnt = 0;
#pragma unroll
        for (int r = 0; r < NN; r += 32) {
            float m = mask[base + r + lane];
            unsigned bal = __ballot_sync(0xffffffffu, m > 0.f);
            int pre = __popc(bal & ((1u << lane) - 1u));
            if (m > 0.f) g_act[base + cnt + pre] = r + lane;
            cnt += __popc(bal);
        }
        if (lane == 0) g_cnt[b] = cnt;
    }
    __syncthreads();

    if (tid < 128) {
        float s = 0.f;
#pragma unroll
        for (int w = 0; w < 32; w++) s += sW[w][tid];
        asum[tid] = s;
    }
    __syncthreads();

    const float cnt = (float)g_cnt[b];

    // qs[m] = sum_d asum[d]*Wq[d,m] + cnt*bq[m]
    if (tid < 128) {
        float q = cnt * bq[tid];
#pragma unroll 8
        for (int d = 0; d < DD; d++) q = fmaf(asum[d], Wq[d * MM + tid], q);
        qs[tid] = q;
    }
    __syncthreads();

    // C = sum_m bk[m]*(qs[m]-bq[m])
    if (warp == 0) {
        float c = 0.f;
        for (int m = lane; m < MM; m += 32) c = fmaf(bk[m], qs[m] - bq[m], c);
        c = warp_sum(c);
        if (lane == 0) g_C[b] = c;
    }

    // G[d] = Wk row d . qs - Wq row d . bk
    {
        float4 qs4 = ((const float4*)qs)[lane];
        float4 bk4 = ((const float4*)bk)[lane];
#pragma unroll
        for (int d = warp; d < DD; d += 32) {
            float p = dot4(Wk4[d * 32 + lane], qs4) - dot4(Wq4[d * 32 + lane], bk4);
            p = warp_sum(p);
            if (lane == 0) g_G[b * DD + d] = p;
        }
    }
}

// ---------------------------------------------------------------------------
// K2: quadratic form, smem-staged. agg_i = A_i.G - A_i M A_i^T + C
// Grid = BB*8, block 256 (8 warps * 8 rows = 64 rows/block).
// ---------------------------------------------------------------------------
__global__ __launch_bounds__(256) void quad_kernel(const float* __restrict__ A)
{
    const int b = blockIdx.x >> 3;
    const int j0 = (blockIdx.x & 7) * 64;
    const int nact = g_cnt[b];
    if (j0 >= nact) return;

    extern __shared__ float4 smem4[];
    float4* sM4 = smem4;                 // [128][32] float4 = 64KB
    float4* sA4 = smem4 + 4096;          // [64][32] float4  = 32KB
    int* sAct = (int*)(smem4 + 4096 + 2048);

    const int warp = threadIdx.x >> 5, lane = threadIdx.x & 31, tid = threadIdx.x;
    const size_t base = (size_t)b * NN;
    const float4* A4 = (const float4*)A;
    const float4* gM4 = (const float4*)g_M;

    if (tid < 64) {
        int j = j0 + tid;
        sAct[tid] = (j < nact) ? g_act[base + j] : -1;
    }
#pragma unroll 4
    for (int idx = tid; idx < 4096; idx += 256) sM4[idx] = gM4[idx];
    __syncthreads();
#pragma unroll 2
    for (int idx = tid; idx < 2048; idx += 256) {
        int r = idx >> 5, c = idx & 31;
        int row = sAct[r];
        sA4[idx] = (row >= 0) ? A4[(base + row) * 32 + c]
                              : make_float4(0.f, 0.f, 0.f, 0.f);
    }
    __syncthreads();

    const int rbase = warp * 8;
    float4 y[8];
#pragma unroll
    for (int r = 0; r < 8; r++) y[r] = make_float4(0.f, 0.f, 0.f, 0.f);

    for (int e4 = 0; e4 < 32; e4++) {
        float4 av[8];
#pragma unroll
        for (int r = 0; r < 8; r++) av[r] = sA4[(rbase + r) * 32 + e4];
#pragma unroll
        for (int s = 0; s < 4; s++) {
            float4 mc = sM4[(e4 * 4 + s) * 32 + lane];
#pragma unroll
            for (int r = 0; r < 8; r++) {
                float a = (s == 0) ? av[r].x : (s == 1) ? av[r].y
                        : (s == 2) ? av[r].z : av[r].w;
                y[r].x = fmaf(a, mc.x, y[r].x);
                y[r].y = fmaf(a, mc.y, y[r].y);
                y[r].z = fmaf(a, mc.z, y[r].z);
                y[r].w = fmaf(a, mc.w, y[r].w);
            }
        }
    }

    float4 G = ((const float4*)(g_G + b * DD))[lane];
    const float C = g_C[b];
#pragma unroll
    for (int r = 0; r < 8; r++) {
        int row = sAct[rbase + r];
        float4 a = sA4[(rbase + r) * 32 + lane];
        float p = a.x * (G.x - y[r].x) + a.y * (G.y - y[r].y)
                + a.z * (G.z - y[r].z) + a.w * (G.w - y[r].w);
        p = warp_sum(p);
        if (lane == 0 && row >= 0) g_agg[base + row] = p + C;
    }
}

// ---------------------------------------------------------------------------
// K3: normalize -> masked softmax -> attn out; context = wsum@Wk + bk
// ---------------------------------------------------------------------------
__global__ __launch_bounds__(1024) void softmax_ctx_kernel(
    const float* __restrict__ A, const float* __restrict__ mask,
    const float* __restrict__ Wk, const float* __restrict__ bk,
    float* __restrict__ out)
{
    const int b = blockIdx.x;
    const int warp = threadIdx.x >> 5, lane = threadIdx.x & 31, tid = threadIdx.x;
    const size_t base = (size_t)b * NN;
    const float4* A4 = (const float4*)A;

    __shared__ float sc[NN];
    __shared__ float sRed[32];
    __shared__ float sW[32][128];
    __shared__ float wsum[128];

    // sum of squares
    float ss = 0.f;
    for (int i = tid; i < NN; i += 1024) {
        float v = g_agg[base + i];
        sc[i] = v;
        ss = fmaf(v, v, ss);
    }
    ss = warp_sum(ss);
    if (lane == 0) sRed[warp] = ss;
    __syncthreads();
    float tot = 0.f;
#pragma unroll
    for (int w = 0; w < 32; w++) tot += sRed[w];
    float inv = rsqrtf(tot);

    // scores + max
    float mx = -INFINITY;
    for (int i = tid; i < NN; i += 1024) {
        float m = mask[base + i];
        float s = (m > 0.f) ? sc[i] * inv : NEG_INF;
        sc[i] = s;
        mx = fmaxf(mx, s);
    }
    mx = warp_max(mx);
    __syncthreads();
    if (lane == 0) sRed[warp] = mx;
    __syncthreads();
    float M = -INFINITY;
#pragma unroll
    for (int w = 0; w < 32; w++) M = fmaxf(M, sRed[w]);

    // exp & sum
    float es = 0.f;
    for (int i = tid; i < NN; i += 1024) {
        float e = __expf(sc[i] - M);
        sc[i] = e;
        es += e;
    }
    es = warp_sum(es);
    __syncthreads();
    if (lane == 0) sRed[warp] = es;
    __syncthreads();
    float S = 0.f;
#pragma unroll
    for (int w = 0; w < 32; w++) S += sRed[w];
    float invS = 1.0f / S;

    // attn out (coalesced)
    for (int i = tid; i < NN; i += 1024) {
        float at = sc[i] * invS;
        sc[i] = at;
        out[base + i] = at;
    }
    __syncthreads();

    // wsum[d] = sum_i attn_i * A_i[d]
    float4 wacc = make_float4(0.f, 0.f, 0.f, 0.f);
#pragma unroll
    for (int i = warp; i < NN; i += 32) {
        float at = sc[i];
        float4 a = A4[(base + i) * 32 + lane];
        wacc.x = fmaf(at, a.x, wacc.x);
        wacc.y = fmaf(at, a.y, wacc.y);
        wacc.z = fmaf(at, a.z, wacc.z);
        wacc.w = fmaf(at, a.w, wacc.w);
    }
    ((float4*)sW[warp])[lane] = wacc;
    __syncthreads();
    if (tid < 128) {
        float s = 0.f;
#pragma unroll
        for (int w = 0; w < 32; w++) s += sW[w][tid];
        wsum[tid] = s;
    }
    __syncthreads();

    // context[m] = sum_d wsum[d]*Wk[d,m] + bk[m]
    if (tid < 128) {
        float c = bk[tid];
#pragma unroll 8
        for (int d = 0; d < DD; d++) c = fmaf(wsum[d], Wk[d * MM + tid], c);
        out[(size_t)BB * NN + (size_t)b * MM + tid] = c;
    }
}

extern "C" void kernel_launch(void* const* d_in, const int* in_sizes, int n_in,
                              void* d_out, int out_size)
{
    const float* A    = (const float*)d_in[0];
    const float* mask = (const float*)d_in[1];
    const float* Wq   = (const float*)d_in[2];
    const float* bq   = (const float*)d_in[3];
    const float* Wk   = (const float*)d_in[4];
    const float* bk   = (const float*)d_in[5];
    float* out = (float*)d_out;

    const int quad_smem = 4096 * 16 + 2048 * 16 + 256;   // 98560 B
    cudaFuncSetAttribute(quad_kernel,
                         cudaFuncAttributeMaxDynamicSharedMemorySize, quad_smem);

    prep_kernel<<<BB + 4, 1024>>>(A, mask, Wq, Wk, bq, bk);
    quad_kernel<<<BB * 8, 256, quad_smem>>>(A);
    softmax_ctx_kernel<<<BB, 1024>>>(A, mask, Wk, bk, out);
}